// round 8
// baseline (speedup 1.0000x reference)
#include <cuda_runtime.h>
#include <cuda_fp16.h>

#define BB 2
#define NN 2048
#define DD 1024
#define HH 16
#define HDD 64
#define ROTD 32
#define MM (BB*NN)

// ---- device scratch (no runtime allocation) ----
__device__ __half g_xh[3u*BB*NN*DD];     // fp16 copies of q,k,v inputs
__device__ __half g_wh[4u*DD*DD];        // fp16 copies of wq,wk,wv,wo
__device__ __half g_qh[BB*HH*NN*HDD];    // (b,h,n,d) rotary Q * 0.125*log2e, fp16
__device__ __half g_kh[BB*HH*NN*HDD];    // (b,h,n,d) rotary K fp16
__device__ __half g_vh[BB*HH*NN*HDD];    // (b,h,n,d) V fp16 (coalesced proj output)
__device__ __half g_vt[BB*HH*NN*HDD];    // (b,h,d,n) V fp16 (PV B layout, via trans)
__device__ __half g_ctxh[BB*NN*DD];      // (b,n,D) attention out fp16
__device__ float g_kt_fb[BB*HH*HDD*NN];  // fallback outputs
__device__ float g_vh_fb[BB*HH*NN*HDD];

// ---- primitives ----
__device__ __forceinline__ void mma16(float& c0, float& c1, float& c2, float& c3,
                                      unsigned a0, unsigned a1, unsigned a2, unsigned a3,
                                      unsigned b0, unsigned b1) {
    asm("mma.sync.aligned.m16n8k16.row.col.f32.f16.f16.f32 "
        "{%0,%1,%2,%3},{%4,%5,%6,%7},{%8,%9},{%0,%1,%2,%3};"
        : "+f"(c0), "+f"(c1), "+f"(c2), "+f"(c3)
        : "r"(a0), "r"(a1), "r"(a2), "r"(a3), "r"(b0), "r"(b1));
}
__device__ __forceinline__ void ldsm4(unsigned& r0, unsigned& r1, unsigned& r2, unsigned& r3,
                                      unsigned addr) {
    asm volatile("ldmatrix.sync.aligned.m8n8.x4.shared.b16 {%0,%1,%2,%3}, [%4];"
                 : "=r"(r0), "=r"(r1), "=r"(r2), "=r"(r3) : "r"(addr));
}
__device__ __forceinline__ void ldsm2(unsigned& r0, unsigned& r1, unsigned addr) {
    asm volatile("ldmatrix.sync.aligned.m8n8.x2.shared.b16 {%0,%1}, [%2];"
                 : "=r"(r0), "=r"(r1) : "r"(addr));
}
__device__ __forceinline__ void cpa16(void* sm, const void* gl) {
    unsigned a = (unsigned)__cvta_generic_to_shared(sm);
    asm volatile("cp.async.cg.shared.global [%0], [%1], 16;\n" :: "r"(a), "l"(gl));
}
#define CP_COMMIT() asm volatile("cp.async.commit_group;\n")
#define CP_WAIT0()  asm volatile("cp.async.wait_group 0;\n")
__device__ __forceinline__ unsigned h2u(float x, float y) {
    __half2 h = __floats2half2_rn(x, y);
    return *reinterpret_cast<unsigned*>(&h);
}
__device__ __forceinline__ unsigned f2h2(float lo, float hi) {
    unsigned r;
    asm("cvt.rn.f16x2.f32 %0, %2, %1;" : "=r"(r) : "f"(lo), "f"(hi));
    return r;
}
__device__ __forceinline__ unsigned hex2(unsigned x) {
    unsigned r;
    asm("ex2.approx.f16x2 %0, %1;" : "=r"(r) : "r"(x));
    return r;
}

// ---- fp32 -> fp16 bulk convert (z selects source tensor) ----
__global__ void cvt_kernel(const float* __restrict__ s0, const float* __restrict__ s1,
                           const float* __restrict__ s2, const float* __restrict__ s3,
                           __half* __restrict__ dst, int per) {
    int z = blockIdx.z;
    const float* s = (z == 0) ? s0 : (z == 1) ? s1 : (z == 2) ? s2 : s3;
    int i = (blockIdx.x * 256 + threadIdx.x) * 4;
    float4 v = *(const float4*)(s + i);
    __half2* d = (__half2*)(dst + (size_t)z * per + i);
    d[0] = __floats2half2_rn(v.x, v.y);
    d[1] = __floats2half2_rn(v.z, v.w);
}

// ============================================================================
// Transpose: coalesced-in / coalesced-out via smem tile.
// z=0: g_kh (b,h,n,d) -> ktp (b,h,d,n) fp32 output
// z=1: g_vh (b,h,n,d) -> g_vt (b,h,d,n) fp16 attention operand
// Fill uses 4B chunks: row stride 132B is only 4B-aligned (8B stores trapped).
// ============================================================================
__global__ void __launch_bounds__(256) trans_kernel(float* __restrict__ ktp) {
    __shared__ __half tile[64][66];
    const int bh = blockIdx.y;
    const int n0 = blockIdx.x * 64;
    const int z = blockIdx.z;
    const __half* src = (z == 0 ? g_kh : g_vh)
                        + (size_t)bh * NN * HDD + (size_t)n0 * HDD;
    const int tid = threadIdx.x;

#pragma unroll
    for (int i = 0; i < 8; i++) {
        int idx = tid + i * 256;             // 2048 x 4B chunks
        int r = idx >> 5, c = (idx & 31) * 2;
        *(unsigned*)&tile[r][c] = *(const unsigned*)&src[(size_t)r * HDD + c];
    }
    __syncthreads();

    const int lane = tid & 31, w = tid >> 5;
    if (z == 0) {
        float* dst = ktp + (size_t)bh * HDD * NN + n0;
#pragma unroll
        for (int dd = 0; dd < 8; dd++) {
            int d = w * 8 + dd;
            float2 v2;
            v2.x = __half2float(tile[2 * lane][d]);
            v2.y = __half2float(tile[2 * lane + 1][d]);
            *(float2*)&dst[(size_t)d * NN + 2 * lane] = v2;
        }
    } else {
        __half* dst = g_vt + (size_t)bh * HDD * NN + n0;
#pragma unroll
        for (int dd = 0; dd < 8; dd++) {
            int d = w * 8 + dd;
            __half2 v2;
            v2.x = tile[2 * lane][d];
            v2.y = tile[2 * lane + 1][d];
            *(__half2*)&dst[(size_t)d * NN + 2 * lane] = v2;
        }
    }
}

// ============================================================================
// Projection GEMM fp16: 128x128 block, BK=32, 256 thr, 2 CTA/SM.
// mode = modeBase + blockIdx.z. All epilogue stores coalesced:
//   0: Q -> rotary * 0.125*log2e -> g_qh | 1: K -> rotary -> g_kh
//   2: V -> vhp (fp32 out) + g_vh        | 3: O (X=g_ctxh) -> out0
// ============================================================================
__global__ void __launch_bounds__(256, 2) proj_mma(
    int modeBase, const float* __restrict__ rot,
    float* __restrict__ out0, float* __restrict__ vhp)
{
    __shared__ __half As[2][128][40];
    __shared__ __half Bs[2][128][40];

    const int mode = modeBase + blockIdx.z;
    const int tid = threadIdx.x, lane = tid & 31, wid = tid >> 5;
    const int g = lane >> 2, t = lane & 3;
    const int wM = wid >> 2, wN = wid & 3;
    const int rowBase = blockIdx.y * 128;
    const int colBase = blockIdx.x * 128;

    const __half* Xp = (mode == 3) ? g_ctxh : (g_xh + (size_t)mode * (BB * NN * DD));
    const __half* Wp = g_wh + (size_t)mode * DD * DD;

    float c[4][4][4];
#pragma unroll
    for (int mt = 0; mt < 4; mt++)
#pragma unroll
        for (int nt = 0; nt < 4; nt++)
#pragma unroll
            for (int r = 0; r < 4; r++) c[mt][nt][r] = 0.f;

    const unsigned asB = (unsigned)__cvta_generic_to_shared(&As[0][0][0]);
    const unsigned bsB = (unsigned)__cvta_generic_to_shared(&Bs[0][0][0]);
    const int arow = (lane & 7) + ((lane >> 3) & 1) * 8, acol = ((lane >> 4) & 1) * 8;
    const int brow = (lane & 7) + ((lane >> 4) & 1) * 8, bcol = ((lane >> 3) & 1) * 8;

#define PJ_COPY(s, k0)                                                              \
    {                                                                               \
        _Pragma("unroll")                                                           \
        for (int tt = 0; tt < 2; tt++) {                                            \
            int cc = tid + tt * 256;                                                \
            int r = cc >> 2, co = (cc & 3) * 8;                                     \
            cpa16(&As[s][r][co], Xp + (size_t)(rowBase + r) * DD + (k0) + co);      \
            cpa16(&Bs[s][r][co], Wp + (size_t)(colBase + r) * DD + (k0) + co);      \
        }                                                                           \
    }

    PJ_COPY(0, 0);
    CP_COMMIT();

    for (int it = 0; it < 32; it++) {
        const int s = it & 1;
        CP_WAIT0();
        __syncthreads();
        if (it < 31) { PJ_COPY(s ^ 1, (it + 1) * 32); CP_COMMIT(); }

#pragma unroll
        for (int kk = 0; kk < 2; kk++) {
            unsigned a[4][4];
#pragma unroll
            for (int mt = 0; mt < 4; mt++)
                ldsm4(a[mt][0], a[mt][1], a[mt][2], a[mt][3],
                      asB + ((unsigned)(s * 128 + wM * 64 + mt * 16 + arow) * 40
                             + kk * 16 + acol) * 2);
            unsigned b[4][2];
#pragma unroll
            for (int np = 0; np < 2; np++)
                ldsm4(b[2 * np][0], b[2 * np][1], b[2 * np + 1][0], b[2 * np + 1][1],
                      bsB + ((unsigned)(s * 128 + wN * 32 + np * 16 + brow) * 40
                             + kk * 16 + bcol) * 2);
#pragma unroll
            for (int mt = 0; mt < 4; mt++)
#pragma unroll
                for (int nt = 0; nt < 4; nt++)
                    mma16(c[mt][nt][0], c[mt][nt][1], c[mt][nt][2], c[mt][nt][3],
                          a[mt][0], a[mt][1], a[mt][2], a[mt][3], b[nt][0], b[nt][1]);
        }
    }
#undef PJ_COPY

#pragma unroll
    for (int mt = 0; mt < 4; mt++)
#pragma unroll
        for (int nt = 0; nt < 4; nt++)
#pragma unroll
            for (int rh = 0; rh < 2; rh++) {
                int row = rowBase + wM * 64 + mt * 16 + g + rh * 8;
                int col = colBase + wN * 32 + nt * 8 + 2 * t;
                float v0 = c[mt][nt][rh * 2], v1 = c[mt][nt][rh * 2 + 1];
                int b = row >> 11, n = row & 2047, h = col >> 6, d = col & 63;

                if ((mode == 0 || mode == 1) && d < ROTD) {
                    float2 f = *(const float2*)&rot[n * ROTD + d];
                    float sn0, cs0, sn1, cs1;
                    __sincosf(f.x, &sn0, &cs0);
                    __sincosf(f.y, &sn1, &cs1);
                    float o0 = v0 * cs0 - v1 * sn0;
                    float o1 = v1 * cs1 + v0 * sn1;
                    v0 = o0; v1 = o1;
                }
                size_t bh = (size_t)b * HH + h;
                if (mode == 0) {
                    const float QS = 0.125f * 1.44269504f;   // 1/8 * log2e
                    *(unsigned*)&g_qh[(bh * NN + n) * HDD + d] = h2u(v0 * QS, v1 * QS);
                } else if (mode == 1) {
                    *(unsigned*)&g_kh[(bh * NN + n) * HDD + d] = h2u(v0, v1);
                } else if (mode == 2) {
                    float2 w2; w2.x = v0; w2.y = v1;
                    *(float2*)&vhp[(bh * NN + n) * HDD + d] = w2;
                    *(unsigned*)&g_vh[(bh * NN + n) * HDD + d] = h2u(v0, v1);
                } else {
                    float2 w2; w2.x = v0; w2.y = v1;
                    *(float2*)&out0[(size_t)row * DD + col] = w2;
                }
            }
}

// ============================================================================
// Flash attention fp16, 3 CTA/SM (12 warps/SM) to cover HMMA+LDSM latency.
// Softmax on SIMD-fp16 + tensor pipes; row sums via ones-row PV mma.
// ============================================================================
__global__ void __launch_bounds__(128, 3) attn_mma() {
    __shared__ __half Ks[2][64][72];
    __shared__ __half Vs[2][72][72];   // rows 64-71: ones row + zero pad (static)

    const int tid = threadIdx.x, lane = tid & 31, wid = tid >> 5;
    const int g = lane >> 2, t = lane & 3;
    const int bh = blockIdx.y;
    const int qBase = blockIdx.x * 128;
    const int m0w = qBase + wid * 32;

    const __half* qhp = g_qh + (size_t)bh * NN * HDD;
    const __half* khp = g_kh + (size_t)bh * NN * HDD;
    const __half* vtp = g_vt + (size_t)bh * NN * HDD;

    for (int e = tid; e < 2 * 8 * 72; e += 128) {
        int s = e / (8 * 72), rr = (e / 72) & 7, j = e % 72;
        Vs[s][64 + rr][j] = __float2half((rr == 0) ? 1.f : 0.f);
    }

    unsigned qa[2][4][4];
#pragma unroll
    for (int mt = 0; mt < 2; mt++)
#pragma unroll
        for (int kk = 0; kk < 4; kk++) {
            const __half* base = qhp + (size_t)(m0w + mt * 16) * HDD + kk * 16 + 2 * t;
            qa[mt][kk][0] = *(const unsigned*)(base + (size_t)g * HDD);
            qa[mt][kk][1] = *(const unsigned*)(base + (size_t)(g + 8) * HDD);
            qa[mt][kk][2] = *(const unsigned*)(base + (size_t)g * HDD + 8);
            qa[mt][kk][3] = *(const unsigned*)(base + (size_t)(g + 8) * HDD + 8);
        }

    float o[2][8][4];
#pragma unroll
    for (int mt = 0; mt < 2; mt++)
#pragma unroll
        for (int nt = 0; nt < 8; nt++)
#pragma unroll
            for (int r = 0; r < 4; r++) o[mt][nt][r] = 0.f;
    float o9[2][4];
#pragma unroll
    for (int mt = 0; mt < 2; mt++)
#pragma unroll
        for (int r = 0; r < 4; r++) o9[mt][r] = 0.f;

    const unsigned ksB = (unsigned)__cvta_generic_to_shared(&Ks[0][0][0]);
    const unsigned vsB = (unsigned)__cvta_generic_to_shared(&Vs[0][0][0]);
    const int brow = (lane & 7) + ((lane >> 4) & 1) * 8, bcol = ((lane >> 3) & 1) * 8;
    const int l16 = lane & 15;
    const int orow = 64 + (l16 & 7), ocol = ((l16 >> 3) & 1) * 8;

#define AT_COPY(s, j0)                                                             \
    {                                                                              \
        _Pragma("unroll")                                                          \
        for (int tt = 0; tt < 8; tt++) {                                           \
            int cc = tid + tt * 128;                                               \
            if (cc < 512) {                                                        \
                int r = cc >> 3, co = (cc & 7) * 8;                                 \
                cpa16(&Ks[s][r][co], khp + (size_t)((j0) + r) * HDD + co);          \
            } else {                                                               \
                int c2 = cc - 512, r = c2 >> 3, co = (c2 & 7) * 8;                  \
                cpa16(&Vs[s][r][co], vtp + (size_t)r * NN + (j0) + co);             \
            }                                                                      \
        }                                                                          \
    }

    AT_COPY(0, 0);
    CP_COMMIT();

    for (int it = 0; it < 32; it++) {
        const int s = it & 1;
        CP_WAIT0();
        __syncthreads();
        if (it < 31) { AT_COPY(s ^ 1, (it + 1) * 64); CP_COMMIT(); }

        // ---- S = Q @ K^T  (log2 domain) ----
        float sc[2][8][4];
#pragma unroll
        for (int mt = 0; mt < 2; mt++)
#pragma unroll
            for (int nt = 0; nt < 8; nt++)
#pragma unroll
                for (int r = 0; r < 4; r++) sc[mt][nt][r] = 0.f;
#pragma unroll
        for (int kk = 0; kk < 4; kk++) {
            unsigned bk[8][2];
#pragma unroll
            for (int np = 0; np < 4; np++)
                ldsm4(bk[2 * np][0], bk[2 * np][1], bk[2 * np + 1][0], bk[2 * np + 1][1],
                      ksB + ((unsigned)(s * 64 + np * 16 + brow) * 72 + kk * 16 + bcol) * 2);
#pragma unroll
            for (int mt = 0; mt < 2; mt++)
#pragma unroll
                for (int nt = 0; nt < 8; nt++)
                    mma16(sc[mt][nt][0], sc[mt][nt][1], sc[mt][nt][2], sc[mt][nt][3],
                          qa[mt][kk][0], qa[mt][kk][1], qa[mt][kk][2], qa[mt][kk][3],
                          bk[nt][0], bk[nt][1]);
        }

        // ---- P = 2^S packed fp16, direct A-fragment layout ----
        unsigned ph[2][4][4];
#pragma unroll
        for (int mt = 0; mt < 2; mt++)
#pragma unroll
            for (int kk = 0; kk < 4; kk++) {
                ph[mt][kk][0] = hex2(f2h2(sc[mt][2 * kk][0],     sc[mt][2 * kk][1]));
                ph[mt][kk][1] = hex2(f2h2(sc[mt][2 * kk][2],     sc[mt][2 * kk][3]));
                ph[mt][kk][2] = hex2(f2h2(sc[mt][2 * kk + 1][0], sc[mt][2 * kk + 1][1]));
                ph[mt][kk][3] = hex2(f2h2(sc[mt][2 * kk + 1][2], sc[mt][2 * kk + 1][3]));
            }

        // ---- O += P @ V  (+ ones-tile for row sums) ----
#pragma unroll
        for (int kk = 0; kk < 4; kk++) {
            unsigned bv[8][2], bl[2];
#pragma unroll
            for (int np = 0; np < 4; np++)
                ldsm4(bv[2 * np][0], bv[2 * np][1], bv[2 * np + 1][0], bv[2 * np + 1][1],
                      vsB + ((unsigned)(s * 72 + np * 16 + brow) * 72 + kk * 16 + bcol) * 2);
            ldsm2(bl[0], bl[1],
                  vsB + ((unsigned)(s * 72 + orow) * 72 + kk * 16 + ocol) * 2);
#pragma unroll
            for (int mt = 0; mt < 2; mt++) {
#pragma unroll
                for (int nt = 0; nt < 8; nt++)
                    mma16(o[mt][nt][0], o[mt][nt][1], o[mt][nt][2], o[mt][nt][3],
                          ph[mt][kk][0], ph[mt][kk][1], ph[mt][kk][2], ph[mt][kk][3],
                          bv[nt][0], bv[nt][1]);
                mma16(o9[mt][0], o9[mt][1], o9[mt][2], o9[mt][3],
                      ph[mt][kk][0], ph[mt][kk][1], ph[mt][kk][2], ph[mt][kk][3],
                      bl[0], bl[1]);
            }
        }
    }
#undef AT_COPY

    const int b = bh >> 4, h = bh & 15;
#pragma unroll
    for (int mt = 0; mt < 2; mt++) {
        float l0 = __shfl_sync(0xffffffffu, o9[mt][0], lane & ~3);
        float l1 = __shfl_sync(0xffffffffu, o9[mt][2], lane & ~3);
        float i0 = 1.f / l0, i1 = 1.f / l1;
        int n0 = m0w + mt * 16 + g;
        __half* c0 = g_ctxh + ((size_t)(b * NN + n0)) * DD + h * HDD;
        __half* c1 = g_ctxh + ((size_t)(b * NN + n0 + 8)) * DD + h * HDD;
#pragma unroll
        for (int nt = 0; nt < 8; nt++) {
            *(unsigned*)&c0[nt * 8 + 2 * t] = h2u(o[mt][nt][0] * i0, o[mt][nt][1] * i0);
            *(unsigned*)&c1[nt * 8 + 2 * t] = h2u(o[mt][nt][2] * i1, o[mt][nt][3] * i1);
        }
    }
}

extern "C" void kernel_launch(void* const* d_in, const int* in_sizes, int n_in,
                              void* d_out, int out_size) {
    const float* q   = (const float*)d_in[0];
    const float* k   = (const float*)d_in[1];
    const float* v   = (const float*)d_in[2];
    const float* wq  = (const float*)d_in[3];
    const float* wk  = (const float*)d_in[4];
    const float* wv  = (const float*)d_in[5];
    const float* wo  = (const float*)d_in[6];
    const float* rot = (const float*)d_in[7];

    float* out0 = (float*)d_out;
    float* ktp; float* vhp;
    const size_t chunk = (size_t)BB * NN * DD;
    if (out_size >= (int)(3 * chunk)) {
        ktp = out0 + chunk;          // concatenated tuple (out, k_t, vh)
        vhp = out0 + 2 * chunk;
    } else {
        cudaGetSymbolAddress((void**)&ktp, g_kt_fb);
        cudaGetSymbolAddress((void**)&vhp, g_vh_fb);
    }

    __half* xh; __half* wh;
    cudaGetSymbolAddress((void**)&xh, g_xh);
    cudaGetSymbolAddress((void**)&wh, g_wh);

    cvt_kernel<<<dim3((BB*NN*DD)/1024, 1, 3), 256>>>(q, k, v, nullptr, xh, BB*NN*DD);
    cvt_kernel<<<dim3((DD*DD)/1024, 1, 4), 256>>>(wq, wk, wv, wo, wh, DD*DD);

    // fused Q/K/V projections: grid (8, 32, 3) = 768 blocks
    proj_mma<<<dim3(DD / 128, MM / 128, 3), 256>>>(0, rot, out0, vhp);

    // K/V transposes: kt output (fp32) + g_vt attention operand (fp16)
    trans_kernel<<<dim3(NN / 64, BB * HH, 2), 256>>>(ktp);

    attn_mma<<<dim3(NN / 128, BB * HH), 128>>>();

    // output projection
    proj_mma<<<dim3(DD / 128, MM / 128, 1), 256>>>(3, rot, out0, vhp);
}